// round 3
// baseline (speedup 1.0000x reference)
#include <cuda_runtime.h>
#include <math.h>

// ---------------------------------------------------------------------------
// Problem constants
// ---------------------------------------------------------------------------
#define BATCH 16
#define NH    128
#define L0    16384
#define KS    4
#define STRIDE 2
#define DEPTHS 13
#define LMAX  8192
#define T_OUT 32            // output positions per block
#define TPT   16            // t's per thread (two halves of 128 threads)
#define TIN   (2*T_OUT + 2) // 66 input positions per tile
#define CIN   129           // 128 h channels + 1 depth channel

// ---------------------------------------------------------------------------
// Device scratch (static, allocation-free)
// ---------------------------------------------------------------------------
__device__ float  g_bufA[(size_t)BATCH * NH * LMAX];
__device__ float  g_bufB[(size_t)BATCH * NH * LMAX];
__device__ float4 g_W4[CIN * 3 * NH];      // [c][gate][o] -> (k0,k1,k2,k3)
__device__ float  g_capture[BATCH * NH];
__device__ int    g_Nseq[BATCH][DEPTHS + 1];
__device__ int    g_finish[BATCH];
__device__ int    g_rank[BATCH];

// ---------------------------------------------------------------------------
// Packed f32x2 FMA (Blackwell)
// ---------------------------------------------------------------------------
__device__ __forceinline__ unsigned long long fma2(unsigned long long a,
                                                   unsigned long long b,
                                                   unsigned long long c)
{
    unsigned long long d;
    asm("fma.rn.f32x2 %0, %1, %2, %3;" : "=l"(d) : "l"(a), "l"(b), "l"(c));
    return d;
}
__device__ __forceinline__ float lane_lo(unsigned long long v)
{ return __uint_as_float((unsigned)(v & 0xffffffffull)); }
__device__ __forceinline__ float lane_hi(unsigned long long v)
{ return __uint_as_float((unsigned)(v >> 32)); }

// ---------------------------------------------------------------------------
// Prep: N recurrence, finish depth, stable rank
// ---------------------------------------------------------------------------
__global__ void prep_meta_kernel(const int* __restrict__ N)
{
    __shared__ int fin[BATCH];
    int b = threadIdx.x;
    if (b < BATCH) {
        int n = N[b];
        g_Nseq[b][0] = n;
        int f = DEPTHS - 1;
        bool done = false;
        #pragma unroll
        for (int d = 0; d < DEPTHS; ++d) {
            int m = n - KS; if (m < 0) m = 0;
            n = (m + 1) / 2 + 1;
            g_Nseq[b][d + 1] = n;
            if (!done && n <= 1) { f = d; done = true; }
        }
        fin[b] = f;
        g_finish[b] = f;
    }
    __syncthreads();
    if (b < BATCH) {
        int f = fin[b];
        int r = 0;
        #pragma unroll
        for (int j = 0; j < BATCH; ++j)
            if (fin[j] < f || (fin[j] == f && j < b)) r++;
        g_rank[b] = r;
    }
}

// ---------------------------------------------------------------------------
// Prep: repack W [384][129][4] -> g_W4[(c*3+gate)*128+o] = float4(k0..k3)
// ---------------------------------------------------------------------------
__global__ void prep_wt_kernel(const float* __restrict__ W)
{
    int i = blockIdx.x * blockDim.x + threadIdx.x;
    if (i < CIN * 3 * NH) {
        int o    = i & 127;
        int gate = (i >> 7) % 3;
        int c    = i / (3 * NH);
        int j    = gate * NH + o;
        const float4* src = reinterpret_cast<const float4*>(W);
        g_W4[i] = src[j * CIN + c];
    }
}

// ---------------------------------------------------------------------------
// One depth step: conv(KS=4, stride=2) + bias + gated update, f32x2-packed.
// 256 threads = 128 output channels x 2 halves of 16 t's each.
// Weight loads software-pipelined one c ahead.
// ---------------------------------------------------------------------------
__global__ __launch_bounds__(256, 1)
void conv_step_kernel(const float* __restrict__ hin,
                      int insel, int outsel,
                      int in_stride, int Lc, int Lout,
                      int depth, float logd,
                      const float* __restrict__ bias)
{
    const int b  = blockIdx.y;
    const int t0 = blockIdx.x * T_OUT;

    const int Nn = g_Nseq[b][depth + 1];
    if (t0 >= Nn) return;   // outputs all dead (masked at next step)

    const float* in = (insel == 0) ? hin : (insel == 1 ? g_bufA : g_bufB);
    float* out = (outsel == 1) ? g_bufA : g_bufB;

    __shared__ float tile[CIN][TIN];   // 129 x 66 floats (264B rows, 8B aligned)

    const int V = min(Lc, g_Nseq[b][depth]);
    const float* inb = in + (size_t)b * NH * in_stride;

    for (int i = threadIdx.x; i < CIN * TIN; i += 256) {
        int c = i / TIN;
        int x = i - c * TIN;
        int pos = 2 * t0 + x;
        float v = 0.0f;
        if (pos < V) v = (c < NH) ? inb[(size_t)c * in_stride + pos] : logd;
        tile[c][x] = v;
    }
    __syncthreads();

    const int o    = threadIdx.x & 127;
    const int half = threadIdx.x >> 7;
    const int tl0  = half * TPT;

    unsigned long long accl[TPT], accr[TPT], accg[TPT];
    #pragma unroll
    for (int tt = 0; tt < TPT; ++tt) { accl[tt] = 0ull; accr[tt] = 0ull; accg[tt] = 0ull; }

    const ulonglong2* wbase = reinterpret_cast<const ulonglong2*>(g_W4);

    // Software pipeline: preload c=0, prefetch c+1 inside the body.
    ulonglong2 wl = wbase[0 * NH + o];
    ulonglong2 wr = wbase[1 * NH + o];
    ulonglong2 wg = wbase[2 * NH + o];

    #pragma unroll 1
    for (int c = 0; c < CIN; ++c) {
        const int cn = (c + 1 < CIN) ? (c + 1) : c;
        ulonglong2 wl_n = wbase[(cn * 3 + 0) * NH + o];
        ulonglong2 wr_n = wbase[(cn * 3 + 1) * NH + o];
        ulonglong2 wg_n = wbase[(cn * 3 + 2) * NH + o];

        const unsigned long long* xr =
            reinterpret_cast<const unsigned long long*>(&tile[c][2 * tl0]);
        unsigned long long x0 = xr[0];
        #pragma unroll
        for (int tt = 0; tt < TPT; ++tt) {
            unsigned long long x1 = xr[tt + 1];
            accl[tt] = fma2(wl.x, x0, accl[tt]);
            accl[tt] = fma2(wl.y, x1, accl[tt]);
            accr[tt] = fma2(wr.x, x0, accr[tt]);
            accr[tt] = fma2(wr.y, x1, accr[tt]);
            accg[tt] = fma2(wg.x, x0, accg[tt]);
            accg[tt] = fma2(wg.y, x1, accg[tt]);
            x0 = x1;
        }
        wl = wl_n; wr = wr_n; wg = wg_n;
    }

    const float bl = bias[o], br = bias[NH + o], bg = bias[2 * NH + o];
    const int fin_here = (g_finish[b] == depth);
    float* outb = out + ((size_t)b * NH + o) * LMAX;

    #pragma unroll
    for (int tt = 0; tt < TPT; ++tt) {
        int t = t0 + tl0 + tt;
        if (t < Lout) {
            float l  = lane_lo(accl[tt]) + lane_hi(accl[tt]) + bl;
            float rr = lane_lo(accr[tt]) + lane_hi(accr[tt]) + br;
            float gg = lane_lo(accg[tt]) + lane_hi(accg[tt]) + bg;
            float g  = 1.0f / (1.0f + __expf(-gg));
            float r  = tanhf(rr);
            float hn = l * g + r * (1.0f - g);
            outb[t] = hn;
            if (t == 0 && fin_here) g_capture[b * NH + o] = hn;
        }
    }
}

// ---------------------------------------------------------------------------
// Final: out[rank[b]] = capture[b]
// ---------------------------------------------------------------------------
__global__ void finalize_kernel(float* __restrict__ out)
{
    int b = blockIdx.x;
    int o = threadIdx.x;
    out[g_rank[b] * NH + o] = g_capture[b * NH + o];
}

// ---------------------------------------------------------------------------
// Launch
// ---------------------------------------------------------------------------
extern "C" void kernel_launch(void* const* d_in, const int* in_sizes, int n_in,
                              void* d_out, int out_size)
{
    const float* h    = (const float*)d_in[0];
    const int*   N    = (const int*)  d_in[1];
    const float* W    = (const float*)d_in[2];
    const float* bias = (const float*)d_in[3];
    float* out = (float*)d_out;

    prep_meta_kernel<<<1, 32>>>(N);
    prep_wt_kernel<<<(CIN * 3 * NH + 255) / 256, 256>>>(W);

    static const int Lin[DEPTHS]   = {16384, 8191, 4095, 2047, 1023, 511, 255,
                                      127, 63, 31, 15, 7, 3};
    static const int LoutA[DEPTHS] = {8191, 4095, 2047, 1023, 511, 255, 127,
                                      63, 31, 15, 7, 3, 1};

    for (int d = 0; d < DEPTHS; ++d) {
        int insel  = (d == 0) ? 0 : ((d & 1) ? 1 : 2);
        int outsel = (d & 1) ? 2 : 1;
        int in_stride = (d == 0) ? L0 : LMAX;
        float logd = log1pf((float)d);
        dim3 grid((LoutA[d] + T_OUT - 1) / T_OUT, BATCH);
        conv_step_kernel<<<grid, 256>>>(h, insel, outsel, in_stride,
                                        Lin[d], LoutA[d], d, logd, bias);
    }

    finalize_kernel<<<BATCH, NH>>>(out);
}

// round 4
// speedup vs baseline: 1.0820x; 1.0820x over previous
#include <cuda_runtime.h>
#include <math.h>

// ---------------------------------------------------------------------------
// Problem constants
// ---------------------------------------------------------------------------
#define BATCH 16
#define NH    128
#define L0    16384
#define KS    4
#define STRIDE 2
#define DEPTHS 13
#define LMAX  8192
#define CIN   129           // 128 h channels + 1 depth channel

// Batched kernel (d = 0..4): tile of 4 t's across all 16 sorted batches
#define BT_OUT 4
#define BTIN_P 5            // even/odd positions needed: x0..x9 -> 5 per parity
#define BROW   6            // padded row (floats) per (c,slot) per parity
#define BTHREADS 512

// Tail kernel (d = 5..12): R2-style per-(slot,tile)
#define TT_OUT 16
#define TTPT   8
#define TTIN   (2*TT_OUT + 2)

typedef unsigned long long ull;

// ---------------------------------------------------------------------------
// Device scratch (static, allocation-free). Buffers are SLOT-major
// (slot = rank of batch when sorted by N descending).
// ---------------------------------------------------------------------------
__device__ float  g_bufA[(size_t)BATCH * NH * LMAX];
__device__ float  g_bufB[(size_t)BATCH * NH * LMAX];
__device__ float4 g_W4[CIN * 3 * NH];        // [c][gate][o] -> (k0,k1,k2,k3)
__device__ float  g_capture[BATCH * NH];     // by slot
__device__ int    g_NS[(DEPTHS + 1) * 16];   // sorted N per depth: [d*16+slot]
__device__ int    g_finS[16];                // finish depth per slot
__device__ int    g_rankS[16];               // output row for slot
__device__ int    g_permS[16];               // original batch index per slot

// ---------------------------------------------------------------------------
// f32x2 helpers
// ---------------------------------------------------------------------------
__device__ __forceinline__ ull fma2(ull a, ull b, ull c)
{
    ull d;
    asm("fma.rn.f32x2 %0, %1, %2, %3;" : "=l"(d) : "l"(a), "l"(b), "l"(c));
    return d;
}
__device__ __forceinline__ ull make2f(float lo, float hi)
{
    ull r;
    asm("mov.b64 %0, {%1, %2};" : "=l"(r) : "f"(lo), "f"(hi));
    return r;
}
__device__ __forceinline__ void unpack2f(ull v, float& lo, float& hi)
{
    asm("mov.b64 {%0, %1}, %2;" : "=f"(lo), "=f"(hi) : "l"(v));
}

// ---------------------------------------------------------------------------
// Prep: N recurrence, finish, rank, argsort(N desc) -> sorted slot tables
// ---------------------------------------------------------------------------
__global__ void prep_meta_kernel(const int* __restrict__ N)
{
    __shared__ int sN[16][DEPTHS + 1];
    __shared__ int sf[16], sr[16], sp[16];
    int t = threadIdx.x;
    if (t < 16) {
        int n = N[t];
        sN[t][0] = n;
        int f = DEPTHS - 1;
        bool done = false;
        #pragma unroll
        for (int d = 0; d < DEPTHS; ++d) {
            int m = n - KS; if (m < 0) m = 0;
            n = (m + 1) / 2 + 1;
            sN[t][d + 1] = n;
            if (!done && n <= 1) { f = d; done = true; }
        }
        sf[t] = f;
    }
    __syncthreads();
    if (t < 16) {
        int f = sf[t], r = 0;
        #pragma unroll
        for (int j = 0; j < 16; ++j)
            if (sf[j] < f || (sf[j] == f && j < t)) r++;
        sr[t] = r;
    }
    __syncthreads();
    if (t == 0) {
        unsigned used = 0;
        for (int s = 0; s < 16; ++s) {
            int best = -1, bestN = -1;
            for (int b = 0; b < 16; ++b) {
                if (used & (1u << b)) continue;
                if (sN[b][0] > bestN) { bestN = sN[b][0]; best = b; }
            }
            used |= 1u << best;
            sp[s] = best;
        }
    }
    __syncthreads();
    if (t < 16) {
        int p = sp[t];
        for (int d = 0; d <= DEPTHS; ++d) g_NS[d * 16 + t] = sN[p][d];
        g_finS[t]  = sf[p];
        g_rankS[t] = sr[p];
        g_permS[t] = p;
    }
}

// ---------------------------------------------------------------------------
// Prep: repack W [384][129][4] -> g_W4[(c*3+gate)*128+o] = float4(k0..k3)
// ---------------------------------------------------------------------------
__global__ void prep_wt_kernel(const float* __restrict__ W)
{
    int i = blockIdx.x * blockDim.x + threadIdx.x;
    if (i < CIN * 3 * NH) {
        int o    = i & 127;
        int gate = (i >> 7) % 3;
        int c    = i / (3 * NH);
        int j    = gate * NH + o;
        const float4* src = reinterpret_cast<const float4*>(W);
        g_W4[i] = src[j * CIN + c];
    }
}

// ---------------------------------------------------------------------------
// Batched depth step (d = 0..4): one block = 4 output t's x ALL 16 slots.
// 512 threads = 128 o x 4 groups; group g owns slots 4g..4g+3 (t-packed f32x2,
// lanes = adjacent t). Alive slots are a prefix (sorted by N desc).
// ---------------------------------------------------------------------------
__global__ __launch_bounds__(BTHREADS, 1)
void conv_batched_kernel(const float* __restrict__ hin,
                         int insel, int outsel,
                         int in_stride, int Lc, int Lout,
                         int depth, float logd,
                         const float* __restrict__ bias)
{
    const int t0 = blockIdx.x * BT_OUT;

    // slot 0 has max N: if even it is dead, whole block is dead
    if (t0 >= g_NS[(depth + 1) * 16 + 0]) return;

    const float* in = (insel == 0) ? hin : (insel == 1 ? g_bufA : g_bufB);
    float* out = (outsel == 1) ? g_bufA : g_bufB;

    extern __shared__ float sm[];
    float* xe = sm;                       // [CIN][16][BROW]
    float* xo = sm + CIN * 16 * BROW;

    const int tid = threadIdx.x;

    // ---- prologue: load x tile (parity-deinterleaved, sorted slots) ----
    {
        const int P = CIN * 16 * BTIN_P;
        for (int i = tid; i < P; i += BTHREADS) {
            int c = i / (16 * BTIN_P);
            int r = i - c * (16 * BTIN_P);
            int s = r / BTIN_P;
            int j = r - s * BTIN_P;
            int V = min(Lc, g_NS[depth * 16 + s]);
            int pos = 2 * t0 + 2 * j;
            float ve = 0.0f, vo = 0.0f;
            if (c == NH) {
                if (pos     < V) ve = logd;
                if (pos + 1 < V) vo = logd;
            } else {
                int src_b = (insel == 0) ? g_permS[s] : s;
                const float* row = in + ((size_t)src_b * NH + c) * in_stride;
                if (pos     < V) ve = row[pos];
                if (pos + 1 < V) vo = row[pos + 1];
            }
            int off = (c * 16 + s) * BROW + j;
            xe[off] = ve;
            xo[off] = vo;
        }
        for (int i = tid; i < CIN * 16; i += BTHREADS) {
            xe[i * BROW + BTIN_P] = 0.0f;
            xo[i * BROW + BTIN_P] = 0.0f;
        }
    }
    __syncthreads();

    const int o = tid & 127;
    const int g = tid >> 7;        // 0..3
    const int slot0 = 4 * g;

    // alive count in this group's prefix
    int A = 0;
    #pragma unroll
    for (int bb = 0; bb < 4; ++bb)
        if (t0 < g_NS[(depth + 1) * 16 + slot0 + bb]) A++;

    // acc[bb][tp]: f32x2, lanes = (t0+2tp, t0+2tp+1)
    ull accL[4][2], accR[4][2], accG[4][2];
    #pragma unroll
    for (int bb = 0; bb < 4; ++bb)
        #pragma unroll
        for (int tp = 0; tp < 2; ++tp) {
            accL[bb][tp] = 0ull; accR[bb][tp] = 0ull; accG[bb][tp] = 0ull;
        }

    if (A > 0) {
        #pragma unroll 1
        for (int c = 0; c < CIN; ++c) {
            const float4 wl4 = g_W4[(c * 3 + 0) * NH + o];
            const float4 wr4 = g_W4[(c * 3 + 1) * NH + o];
            const float4 wg4 = g_W4[(c * 3 + 2) * NH + o];
            const ull wl0 = make2f(wl4.x, wl4.x), wl1 = make2f(wl4.y, wl4.y),
                      wl2 = make2f(wl4.z, wl4.z), wl3 = make2f(wl4.w, wl4.w);
            const ull wr0 = make2f(wr4.x, wr4.x), wr1 = make2f(wr4.y, wr4.y),
                      wr2 = make2f(wr4.z, wr4.z), wr3 = make2f(wr4.w, wr4.w);
            const ull wg0 = make2f(wg4.x, wg4.x), wg1 = make2f(wg4.y, wg4.y),
                      wg2 = make2f(wg4.z, wg4.z), wg3 = make2f(wg4.w, wg4.w);

            const float* xec = xe + (c * 16 + slot0) * BROW;
            const float* xoc = xo + (c * 16 + slot0) * BROW;

            #pragma unroll
            for (int bb = 0; bb < 4; ++bb) {
                if (bb < A) {
                    const float2* pe = reinterpret_cast<const float2*>(xec + bb * BROW);
                    const float2* po = reinterpret_cast<const float2*>(xoc + bb * BROW);
                    float2 e01 = pe[0], e23 = pe[1], e45 = pe[2];
                    float2 o01 = po[0], o23 = po[1], o45 = po[2];
                    // pairs over t: (t, t+1)
                    ull u0 = make2f(e01.x, e01.y);   // (xe0, xe1)
                    ull u1 = make2f(e01.y, e23.x);   // (xe1, xe2)
                    ull u2 = make2f(e23.x, e23.y);   // (xe2, xe3)
                    ull u3 = make2f(e23.y, e45.x);   // (xe3, xe4)
                    ull v0 = make2f(o01.x, o01.y);
                    ull v1 = make2f(o01.y, o23.x);
                    ull v2 = make2f(o23.x, o23.y);
                    ull v3 = make2f(o23.y, o45.x);

                    accL[bb][0] = fma2(wl0, u0, accL[bb][0]);
                    accL[bb][0] = fma2(wl1, v0, accL[bb][0]);
                    accL[bb][0] = fma2(wl2, u1, accL[bb][0]);
                    accL[bb][0] = fma2(wl3, v1, accL[bb][0]);
                    accR[bb][0] = fma2(wr0, u0, accR[bb][0]);
                    accR[bb][0] = fma2(wr1, v0, accR[bb][0]);
                    accR[bb][0] = fma2(wr2, u1, accR[bb][0]);
                    accR[bb][0] = fma2(wr3, v1, accR[bb][0]);
                    accG[bb][0] = fma2(wg0, u0, accG[bb][0]);
                    accG[bb][0] = fma2(wg1, v0, accG[bb][0]);
                    accG[bb][0] = fma2(wg2, u1, accG[bb][0]);
                    accG[bb][0] = fma2(wg3, v1, accG[bb][0]);

                    accL[bb][1] = fma2(wl0, u2, accL[bb][1]);
                    accL[bb][1] = fma2(wl1, v2, accL[bb][1]);
                    accL[bb][1] = fma2(wl2, u3, accL[bb][1]);
                    accL[bb][1] = fma2(wl3, v3, accL[bb][1]);
                    accR[bb][1] = fma2(wr0, u2, accR[bb][1]);
                    accR[bb][1] = fma2(wr1, v2, accR[bb][1]);
                    accR[bb][1] = fma2(wr2, u3, accR[bb][1]);
                    accR[bb][1] = fma2(wr3, v3, accR[bb][1]);
                    accG[bb][1] = fma2(wg0, u2, accG[bb][1]);
                    accG[bb][1] = fma2(wg1, v2, accG[bb][1]);
                    accG[bb][1] = fma2(wg2, u3, accG[bb][1]);
                    accG[bb][1] = fma2(wg3, v3, accG[bb][1]);
                }
            }
        }
    }

    // ---- epilogue ----
    const float bl = bias[o], br = bias[NH + o], bg = bias[2 * NH + o];
    #pragma unroll
    for (int bb = 0; bb < 4; ++bb) {
        if (bb < A) {
            const int slot = slot0 + bb;
            const int fin_here = (g_finS[slot] == depth);
            float* outb = out + ((size_t)slot * NH + o) * LMAX;
            #pragma unroll
            for (int tp = 0; tp < 2; ++tp) {
                float l0, l1, r0, r1, gg0, gg1;
                unpack2f(accL[bb][tp], l0, l1);
                unpack2f(accR[bb][tp], r0, r1);
                unpack2f(accG[bb][tp], gg0, gg1);
                #pragma unroll
                for (int lane = 0; lane < 2; ++lane) {
                    int t = t0 + 2 * tp + lane;
                    if (t < Lout) {
                        float l  = (lane ? l1 : l0) + bl;
                        float rr = (lane ? r1 : r0) + br;
                        float ga = (lane ? gg1 : gg0) + bg;
                        float gv = 1.0f / (1.0f + __expf(-ga));
                        float rv = tanhf(rr);
                        float hn = l * gv + rv * (1.0f - gv);
                        outb[t] = hn;
                        if (t == 0 && fin_here) g_capture[slot * NH + o] = hn;
                    }
                }
            }
        }
    }
}

// ---------------------------------------------------------------------------
// Tail depth step (d = 5..12): R2-style per-(slot, tile), K-packed f32x2.
// ---------------------------------------------------------------------------
__global__ __launch_bounds__(256)
void conv_tail_kernel(int insel, int outsel,
                      int Lc, int Lout,
                      int depth, float logd,
                      const float* __restrict__ bias)
{
    const int s  = blockIdx.y;
    const int t0 = blockIdx.x * TT_OUT;

    const int Nn = g_NS[(depth + 1) * 16 + s];
    if (t0 >= Nn) return;

    const float* in = (insel == 1) ? g_bufA : g_bufB;
    float* out = (outsel == 1) ? g_bufA : g_bufB;

    __shared__ float tile[CIN][TTIN];

    const int V = min(Lc, g_NS[depth * 16 + s]);
    const float* inb = in + (size_t)s * NH * LMAX;

    for (int i = threadIdx.x; i < CIN * TTIN; i += 256) {
        int c = i / TTIN;
        int x = i - c * TTIN;
        int pos = 2 * t0 + x;
        float v = 0.0f;
        if (pos < V) v = (c < NH) ? inb[(size_t)c * LMAX + pos] : logd;
        tile[c][x] = v;
    }
    __syncthreads();

    const int o    = threadIdx.x & 127;
    const int half = threadIdx.x >> 7;
    const int tl0  = half * TTPT;

    ull accl[TTPT], accr[TTPT], accg[TTPT];
    #pragma unroll
    for (int tt = 0; tt < TTPT; ++tt) { accl[tt] = 0ull; accr[tt] = 0ull; accg[tt] = 0ull; }

    const ulonglong2* wbase = reinterpret_cast<const ulonglong2*>(g_W4);

    #pragma unroll 1
    for (int c = 0; c < CIN; ++c) {
        const ulonglong2 wl = wbase[(c * 3 + 0) * NH + o];
        const ulonglong2 wr = wbase[(c * 3 + 1) * NH + o];
        const ulonglong2 wg = wbase[(c * 3 + 2) * NH + o];
        const ull* xr = reinterpret_cast<const ull*>(&tile[c][2 * tl0]);
        ull x0 = xr[0];
        #pragma unroll
        for (int tt = 0; tt < TTPT; ++tt) {
            ull x1 = xr[tt + 1];
            accl[tt] = fma2(wl.x, x0, accl[tt]);
            accl[tt] = fma2(wl.y, x1, accl[tt]);
            accr[tt] = fma2(wr.x, x0, accr[tt]);
            accr[tt] = fma2(wr.y, x1, accr[tt]);
            accg[tt] = fma2(wg.x, x0, accg[tt]);
            accg[tt] = fma2(wg.y, x1, accg[tt]);
            x0 = x1;
        }
    }

    const float bl = bias[o], br = bias[NH + o], bg = bias[2 * NH + o];
    const int fin_here = (g_finS[s] == depth);
    float* outb = out + ((size_t)s * NH + o) * LMAX;

    #pragma unroll
    for (int tt = 0; tt < TTPT; ++tt) {
        int t = t0 + tl0 + tt;
        if (t < Lout) {
            float lo, hi;
            unpack2f(accl[tt], lo, hi); float l  = lo + hi + bl;
            unpack2f(accr[tt], lo, hi); float rr = lo + hi + br;
            unpack2f(accg[tt], lo, hi); float ga = lo + hi + bg;
            float gv = 1.0f / (1.0f + __expf(-ga));
            float rv = tanhf(rr);
            float hn = l * gv + rv * (1.0f - gv);
            outb[t] = hn;
            if (t == 0 && fin_here) g_capture[s * NH + o] = hn;
        }
    }
}

// ---------------------------------------------------------------------------
// Final: out[rankS[s]] = capture[s]
// ---------------------------------------------------------------------------
__global__ void finalize_kernel(float* __restrict__ out)
{
    int s = blockIdx.x;
    int o = threadIdx.x;
    out[g_rankS[s] * NH + o] = g_capture[s * NH + o];
}

// ---------------------------------------------------------------------------
// Launch
// ---------------------------------------------------------------------------
extern "C" void kernel_launch(void* const* d_in, const int* in_sizes, int n_in,
                              void* d_out, int out_size)
{
    const float* h    = (const float*)d_in[0];
    const int*   N    = (const int*)  d_in[1];
    const float* W    = (const float*)d_in[2];
    const float* bias = (const float*)d_in[3];
    float* out = (float*)d_out;

    const int SMEM_DYN = 2 * CIN * 16 * BROW * (int)sizeof(float);  // 99072 B
    cudaFuncSetAttribute(conv_batched_kernel,
                         cudaFuncAttributeMaxDynamicSharedMemorySize, SMEM_DYN);

    prep_meta_kernel<<<1, 32>>>(N);
    prep_wt_kernel<<<(CIN * 3 * NH + 255) / 256, 256>>>(W);

    static const int Lin[DEPTHS]   = {16384, 8191, 4095, 2047, 1023, 511, 255,
                                      127, 63, 31, 15, 7, 3};
    static const int LoutA[DEPTHS] = {8191, 4095, 2047, 1023, 511, 255, 127,
                                      63, 31, 15, 7, 3, 1};

    for (int d = 0; d < DEPTHS; ++d) {
        int insel  = (d == 0) ? 0 : ((d & 1) ? 1 : 2);
        int outsel = (d & 1) ? 2 : 1;
        int in_stride = (d == 0) ? L0 : LMAX;
        float logd = log1pf((float)d);
        if (d <= 4) {
            dim3 grid((LoutA[d] + BT_OUT - 1) / BT_OUT);
            conv_batched_kernel<<<grid, BTHREADS, SMEM_DYN>>>(
                h, insel, outsel, in_stride, Lin[d], LoutA[d], d, logd, bias);
        } else {
            dim3 grid((LoutA[d] + TT_OUT - 1) / TT_OUT, BATCH);
            conv_tail_kernel<<<grid, 256>>>(insel, outsel,
                                            Lin[d], LoutA[d], d, logd, bias);
        }
    }

    finalize_kernel<<<BATCH, NH>>>(out);
}

// round 5
// speedup vs baseline: 1.3299x; 1.2291x over previous
#include <cuda_runtime.h>
#include <math.h>

// ---------------------------------------------------------------------------
// Problem constants
// ---------------------------------------------------------------------------
#define BATCH 16
#define NH    128
#define L0    16384
#define KS    4
#define STRIDE 2
#define DEPTHS 13
#define LMAX  8192
#define CIN   129           // 128 h channels + 1 depth channel

#define T_OUT 32            // output positions per block
#define TIN   68            // input positions per tile (2*32+2, padded to 68 for ull2)
#define NTHREADS 384        // 3 gates x 128 output channels

typedef unsigned long long ull;

// ---------------------------------------------------------------------------
// Device scratch (static, allocation-free)
// ---------------------------------------------------------------------------
__device__ float  g_bufA[(size_t)BATCH * NH * LMAX];
__device__ float  g_bufB[(size_t)BATCH * NH * LMAX];
__device__ float4 g_W4[CIN * 3 * NH];        // [c][gate][o] -> (k0,k1,k2,k3)
__device__ float  g_capture[BATCH * NH];
__device__ int    g_Nseq[BATCH][DEPTHS + 1];
__device__ int    g_finish[BATCH];
__device__ int    g_rank[BATCH];

// ---------------------------------------------------------------------------
// f32x2 helpers
// ---------------------------------------------------------------------------
__device__ __forceinline__ ull fma2(ull a, ull b, ull c)
{
    ull d;
    asm("fma.rn.f32x2 %0, %1, %2, %3;" : "=l"(d) : "l"(a), "l"(b), "l"(c));
    return d;
}
__device__ __forceinline__ void unpack2f(ull v, float& lo, float& hi)
{
    asm("mov.b64 {%0, %1}, %2;" : "=f"(lo), "=f"(hi) : "l"(v));
}

// ---------------------------------------------------------------------------
// Prep: N recurrence, finish depth, stable rank
// ---------------------------------------------------------------------------
__global__ void prep_meta_kernel(const int* __restrict__ N)
{
    __shared__ int fin[BATCH];
    int b = threadIdx.x;
    if (b < BATCH) {
        int n = N[b];
        g_Nseq[b][0] = n;
        int f = DEPTHS - 1;
        bool done = false;
        #pragma unroll
        for (int d = 0; d < DEPTHS; ++d) {
            int m = n - KS; if (m < 0) m = 0;
            n = (m + 1) / 2 + 1;
            g_Nseq[b][d + 1] = n;
            if (!done && n <= 1) { f = d; done = true; }
        }
        fin[b] = f;
        g_finish[b] = f;
    }
    __syncthreads();
    if (b < BATCH) {
        int f = fin[b];
        int r = 0;
        #pragma unroll
        for (int j = 0; j < BATCH; ++j)
            if (fin[j] < f || (fin[j] == f && j < b)) r++;
        g_rank[b] = r;
    }
}

// ---------------------------------------------------------------------------
// Prep: repack W [384][129][4] -> g_W4[(c*3+gate)*128+o] = float4(k0..k3)
// ---------------------------------------------------------------------------
__global__ void prep_wt_kernel(const float* __restrict__ W)
{
    int i = blockIdx.x * blockDim.x + threadIdx.x;
    if (i < CIN * 3 * NH) {
        int o    = i & 127;
        int gate = (i >> 7) % 3;
        int c    = i / (3 * NH);
        int j    = gate * NH + o;
        const float4* src = reinterpret_cast<const float4*>(W);
        g_W4[i] = src[j * CIN + c];
    }
}

// ---------------------------------------------------------------------------
// One depth step: conv(KS=4, stride=2) + bias + gated update.
// 384 threads: thread = (gate, o). Each thread computes its gate's pre-
// activation for all 32 t's of the tile (K-packed f32x2, 1 weight LDG.128
// per c, prefetched one c ahead). Gates recombine via smem epilogue.
// ---------------------------------------------------------------------------
__global__ __launch_bounds__(NTHREADS, 1)
void conv_step_kernel(const float* __restrict__ hin,
                      int insel, int outsel,
                      int in_stride, int Lc, int Lout,
                      int depth, float logd,
                      const float* __restrict__ bias)
{
    const int b  = blockIdx.y;
    const int t0 = blockIdx.x * T_OUT;

    const int Nn = g_Nseq[b][depth + 1];
    if (t0 >= Nn) return;   // all outputs of this tile are dead downstream

    const float* in = (insel == 0) ? hin : (insel == 1 ? g_bufA : g_bufB);
    float* out = (outsel == 1) ? g_bufA : g_bufB;

    // union: x tile (CIN*TIN = 8772 floats, 35088B) then gate-sum epilogue
    // (3*128*32 = 12288 floats, 49152B). Both phases separated by syncs.
    __shared__ __align__(16) float smu[3 * NH * T_OUT];  // 49152 B
    float* tile = smu;            // [CIN][TIN]
    float* epi  = smu;            // [gate][t][o]

    const int tid = threadIdx.x;

    // ---- load x tile ----
    const int V = min(Lc, g_Nseq[b][depth]);
    const float* inb = in + (size_t)b * NH * in_stride;
    for (int i = tid; i < CIN * TIN; i += NTHREADS) {
        int c = i / TIN;
        int x = i - c * TIN;
        int pos = 2 * t0 + x;
        float v = 0.0f;
        if (pos < V) v = (c < NH) ? inb[(size_t)c * in_stride + pos] : logd;
        tile[i] = v;
    }
    __syncthreads();

    const int o    = tid & 127;
    const int gate = tid >> 7;          // 0..2

    ull acc[T_OUT];
    #pragma unroll
    for (int t = 0; t < T_OUT; ++t) acc[t] = 0ull;

    // weight pointer for this (gate, o); stride 384 float4 per c
    const ulonglong2* wp =
        reinterpret_cast<const ulonglong2*>(g_W4) + gate * NH + o;
    ulonglong2 w = *wp;                  // (k0,k1) | (k2,k3)

    #pragma unroll 1
    for (int c = 0; c < CIN; ++c) {
        // prefetch next c's weights (reload last on final iter; harmless)
        const ulonglong2* wpn = wp + ((c < CIN - 1) ? 3 * NH : 0);
        ulonglong2 wn = *wpn;

        // x row as ulonglong2: q2[j] = (xr[2j], xr[2j+1]),
        // xr[t] = (x[2t], x[2t+1]) packed pairs
        const ulonglong2* q2 =
            reinterpret_cast<const ulonglong2*>(tile + c * TIN);
        ulonglong2 v = q2[0];
        #pragma unroll
        for (int j = 0; j < T_OUT / 2; ++j) {
            ulonglong2 vn = q2[j + 1];
            // t = 2j:   x0 = xr[2j] = v.x,  x1 = xr[2j+1] = v.y
            acc[2 * j]     = fma2(w.x, v.x, acc[2 * j]);
            acc[2 * j]     = fma2(w.y, v.y, acc[2 * j]);
            // t = 2j+1: x0 = xr[2j+1] = v.y, x1 = xr[2j+2] = vn.x
            acc[2 * j + 1] = fma2(w.x, v.y, acc[2 * j + 1]);
            acc[2 * j + 1] = fma2(w.y, vn.x, acc[2 * j + 1]);
            v = vn;
        }
        w = wn;
        wp = wpn;
    }

    // ---- epilogue: recombine gates through smem ----
    __syncthreads();   // all warps done reading tile before overwrite

    const float bgo = bias[gate * NH + o];
    #pragma unroll
    for (int t = 0; t < T_OUT; ++t) {
        float lo, hi;
        unpack2f(acc[t], lo, hi);
        epi[gate * (NH * T_OUT) + t * NH + o] = lo + hi + bgo;
    }
    __syncthreads();

    const int fin_here = (g_finish[b] == depth);
    float* outb = out + ((size_t)b * NH) * LMAX;
    for (int i = tid; i < NH * T_OUT; i += NTHREADS) {
        int t  = i >> 7;
        int oo = i & 127;
        int tg = t0 + t;
        if (tg < Lout) {
            float l  = epi[0 * (NH * T_OUT) + i];
            float rr = epi[1 * (NH * T_OUT) + i];
            float ga = epi[2 * (NH * T_OUT) + i];
            float gv = 1.0f / (1.0f + __expf(-ga));
            float e2 = __expf(2.0f * rr);
            float rv = (e2 - 1.0f) / (e2 + 1.0f);   // tanh
            float hn = l * gv + rv * (1.0f - gv);
            outb[(size_t)oo * LMAX + tg] = hn;
            if (tg == 0 && fin_here) g_capture[b * NH + oo] = hn;
        }
    }
}

// ---------------------------------------------------------------------------
// Final: out[rank[b]] = capture[b]
// ---------------------------------------------------------------------------
__global__ void finalize_kernel(float* __restrict__ out)
{
    int b = blockIdx.x;
    int o = threadIdx.x;
    out[g_rank[b] * NH + o] = g_capture[b * NH + o];
}

// ---------------------------------------------------------------------------
// Launch
// ---------------------------------------------------------------------------
extern "C" void kernel_launch(void* const* d_in, const int* in_sizes, int n_in,
                              void* d_out, int out_size)
{
    const float* h    = (const float*)d_in[0];
    const int*   N    = (const int*)  d_in[1];
    const float* W    = (const float*)d_in[2];
    const float* bias = (const float*)d_in[3];
    float* out = (float*)d_out;

    prep_meta_kernel<<<1, 32>>>(N);
    prep_wt_kernel<<<(CIN * 3 * NH + 255) / 256, 256>>>(W);

    static const int Lin[DEPTHS]   = {16384, 8191, 4095, 2047, 1023, 511, 255,
                                      127, 63, 31, 15, 7, 3};
    static const int LoutA[DEPTHS] = {8191, 4095, 2047, 1023, 511, 255, 127,
                                      63, 31, 15, 7, 3, 1};

    for (int d = 0; d < DEPTHS; ++d) {
        int insel  = (d == 0) ? 0 : ((d & 1) ? 1 : 2);
        int outsel = (d & 1) ? 2 : 1;
        int in_stride = (d == 0) ? L0 : LMAX;
        float logd = log1pf((float)d);
        dim3 grid((LoutA[d] + T_OUT - 1) / T_OUT, BATCH);
        conv_step_kernel<<<grid, NTHREADS>>>(h, insel, outsel, in_stride,
                                             Lin[d], LoutA[d], d, logd, bias);
    }

    finalize_kernel<<<BATCH, NH>>>(out);
}